// round 1
// baseline (speedup 1.0000x reference)
#include <cuda_runtime.h>
#include <cuda_bf16.h>

#define NN 50000
#define EE 400000
#define DD 300
#define DP 304      // padded feature dim (multiple of 8, float4-aligned rows)
#define LL 5
#define CC 128
#define NGG 256
#define BN_EPS 1e-5f

// ---------------- device scratch (no allocs allowed) ----------------
__device__ float g_h[NN * DP];        // current node features (pad cols = 0)
__device__ float g_agg[NN * DP];      // h + aggregated neighbors / post-BN1 activations
__device__ float g_z[NN * DP];        // GEMM outputs
__device__ float g_W[2 * LL * DP * DP];  // padded weights: [which][layer][DP][DP]
__device__ float g_bias[2 * LL * DP];    // padded biases
__device__ float g_pooled[(LL + 1) * NGG * DP];
__device__ float g_cnt[NGG];
__device__ float g_sum[DP];
__device__ float g_sq[DP];
__device__ int   g_edge[2 * EE];      // src[EE], dst[EE] as int32
__device__ int   g_batch[NN];
__device__ int   g_flag[2];           // 1 => raw data is int32, 0 => int64

// ---------------- small utility kernels ----------------
__global__ void k_zero_flags() {
    if (threadIdx.x < 2) g_flag[threadIdx.x] = 0;
}

// Scan odd 32-bit words of the first nwords words. If any nonzero -> data is int32.
__global__ void k_detect(const int* __restrict__ raw, int nwords, int slot) {
    int stride = gridDim.x * blockDim.x;
    for (int i = blockIdx.x * blockDim.x + threadIdx.x; 2 * i + 1 < nwords; i += stride) {
        if (raw[2 * i + 1] != 0) g_flag[slot] = 1;  // benign race
    }
}

__global__ void k_convert_edge(const void* __restrict__ raw) {
    int i = blockIdx.x * blockDim.x + threadIdx.x;
    if (i >= 2 * EE) return;
    if (g_flag[0]) g_edge[i] = ((const int*)raw)[i];
    else           g_edge[i] = (int)((const long long*)raw)[i];
}

__global__ void k_convert_batch(const void* __restrict__ raw) {
    int i = blockIdx.x * blockDim.x + threadIdx.x;
    if (i >= NN) return;
    if (g_flag[1]) g_batch[i] = ((const int*)raw)[i];
    else           g_batch[i] = (int)((const long long*)raw)[i];
}

// Pad MLP weights [L,300,300] -> g_W [2][L][304][304] (zero padding)
__global__ void k_padW(const float* __restrict__ W1, const float* __restrict__ W2) {
    int total = 2 * LL * DP * DP;
    int stride = gridDim.x * blockDim.x;
    for (int idx = blockIdx.x * blockDim.x + threadIdx.x; idx < total; idx += stride) {
        int c = idx % DP;
        int r = (idx / DP) % DP;
        int l = (idx / (DP * DP)) % LL;
        int w = idx / (DP * DP * LL);
        float v = 0.f;
        if (r < DD && c < DD) {
            const float* W = w ? W2 : W1;
            v = W[(l * DD + r) * DD + c];
        }
        g_W[idx] = v;
    }
}

__global__ void k_padB(const float* __restrict__ b1, const float* __restrict__ b2) {
    int total = 2 * LL * DP;
    int idx = blockIdx.x * blockDim.x + threadIdx.x;
    if (idx >= total) return;
    int c = idx % DP;
    int l = (idx / DP) % LL;
    int w = idx / (DP * LL);
    float v = 0.f;
    if (c < DD) v = (w ? b2 : b1)[l * DD + c];
    g_bias[idx] = v;
}

// Restride x [N,300] -> g_h [N,304] (pad zero)
__global__ void k_init_h(const float* __restrict__ x) {
    int total = NN * DP;
    int stride = gridDim.x * blockDim.x;
    for (int idx = blockIdx.x * blockDim.x + threadIdx.x; idx < total; idx += stride) {
        int c = idx % DP;
        int n = idx / DP;
        g_h[idx] = (c < DD) ? x[n * DD + c] : 0.f;
    }
}

__global__ void k_zero_pool() {
    int total = (LL + 1) * NGG * DP;
    int stride = gridDim.x * blockDim.x;
    for (int idx = blockIdx.x * blockDim.x + threadIdx.x; idx < total; idx += stride) {
        g_pooled[idx] = 0.f;
        if (idx < NGG) g_cnt[idx] = 0.f;
    }
}

__global__ void k_zero_stats() {
    int i = threadIdx.x;
    if (i < DP) { g_sum[i] = 0.f; g_sq[i] = 0.f; }
}

__global__ void k_counts() {
    int i = blockIdx.x * blockDim.x + threadIdx.x;
    if (i < NN) atomicAdd(&g_cnt[g_batch[i]], 1.0f);
}

// copy g_h -> g_agg (float4)
__global__ void k_copy() {
    int total = NN * DP / 4;
    int stride = gridDim.x * blockDim.x;
    const float4* s = (const float4*)g_h;
    float4* d = (float4*)g_agg;
    for (int i = blockIdx.x * blockDim.x + threadIdx.x; i < total; i += stride)
        d[i] = s[i];
}

// One warp per edge: g_agg[dst] += g_h[src], vector float4 atomics
__global__ void k_scatter() {
    int warp = (blockIdx.x * blockDim.x + threadIdx.x) >> 5;
    int lane = threadIdx.x & 31;
    if (warp >= EE) return;
    int s = g_edge[warp];
    int t = g_edge[EE + warp];
    const float4* srow = (const float4*)(g_h + (long)s * DP);
    float4* drow = (float4*)(g_agg + (long)t * DP);
#pragma unroll 3
    for (int c = lane; c < DD / 4; c += 32) {
        float4 v = srow[c];
        atomicAdd(&drow[c], v);
    }
}

// One warp per node: g_pooled[depth][batch[n]] += g_h[n]
__global__ void k_pool(int depth) {
    int warp = (blockIdx.x * blockDim.x + threadIdx.x) >> 5;
    int lane = threadIdx.x & 31;
    if (warp >= NN) return;
    int g = g_batch[warp];
    const float4* srow = (const float4*)(g_h + (long)warp * DP);
    float4* drow = (float4*)(g_pooled + ((long)depth * NGG + g) * DP);
#pragma unroll 3
    for (int c = lane; c < DD / 4; c += 32) {
        float4 v = srow[c];
        atomicAdd(&drow[c], v);
    }
}

// ---------------- SGEMM: g_z[M,DP] = g_agg[M,DP] @ W + bias ----------------
#define GBM 128
#define GBN 128
#define GBK 8
__global__ void __launch_bounds__(256, 2) k_gemm(int which, int layer) {
    const float* __restrict__ B = g_W + ((long)which * LL + layer) * DP * DP;
    const float* __restrict__ bias = g_bias + ((long)which * LL + layer) * DP;
    __shared__ float As[GBK][GBM];
    __shared__ float Bs[GBK][GBN];
    int bn = blockIdx.x * GBN;
    int bm = blockIdx.y * GBM;
    int tid = threadIdx.x;
    int tx = (tid % 16) * 8;  // col offset within tile
    int ty = (tid / 16) * 8;  // row offset within tile
    float acc[8][8];
#pragma unroll
    for (int i = 0; i < 8; i++)
#pragma unroll
        for (int j = 0; j < 8; j++) acc[i][j] = 0.f;

    int arow = tid >> 1;          // 0..127
    int acol = (tid & 1) * 4;     // 0 or 4
    int brow = tid >> 5;          // 0..7
    int bcol = (tid & 31) * 4;    // 0..124

    for (int k0 = 0; k0 < DP; k0 += GBK) {
        // load A tile (transposed into As[k][m])
        {
            int gr = bm + arow;
            float4 v = make_float4(0.f, 0.f, 0.f, 0.f);
            if (gr < NN) v = *(const float4*)(g_agg + (long)gr * DP + k0 + acol);
            As[acol + 0][arow] = v.x;
            As[acol + 1][arow] = v.y;
            As[acol + 2][arow] = v.z;
            As[acol + 3][arow] = v.w;
        }
        // load B tile
        {
            int gc = bn + bcol;
            float4 v = make_float4(0.f, 0.f, 0.f, 0.f);
            if (gc < DP) v = *(const float4*)(B + (long)(k0 + brow) * DP + gc);
            *(float4*)&Bs[brow][bcol] = v;
        }
        __syncthreads();
#pragma unroll
        for (int k = 0; k < GBK; ++k) {
            float4 a0 = *(const float4*)&As[k][ty];
            float4 a1 = *(const float4*)&As[k][ty + 4];
            float4 b0 = *(const float4*)&Bs[k][tx];
            float4 b1 = *(const float4*)&Bs[k][tx + 4];
            float ra[8] = {a0.x, a0.y, a0.z, a0.w, a1.x, a1.y, a1.z, a1.w};
            float rb[8] = {b0.x, b0.y, b0.z, b0.w, b1.x, b1.y, b1.z, b1.w};
#pragma unroll
            for (int i = 0; i < 8; i++)
#pragma unroll
                for (int j = 0; j < 8; j++) acc[i][j] += ra[i] * rb[j];
        }
        __syncthreads();
    }
    // epilogue: + bias, store (pad cols get 0+0 -> keeps pad invariant)
#pragma unroll
    for (int i = 0; i < 8; i++) {
        int gr = bm + ty + i;
        if (gr >= NN) break;
#pragma unroll
        for (int j = 0; j < 8; j++) {
            int gc = bn + tx + j;
            if (gc < DP) g_z[(long)gr * DP + gc] = acc[i][j] + bias[gc];
        }
    }
}

// ---------------- BN stats: per-column sum & sumsq over g_z ----------------
__global__ void k_colstats() {
    int t = threadIdx.x;  // 128
    int r0 = blockIdx.x * 128;
    int rend = min(r0 + 128, NN);
    float s0 = 0.f, q0 = 0.f, s1 = 0.f, q1 = 0.f, s2 = 0.f, q2 = 0.f;
    for (int r = r0; r < rend; ++r) {
        const float* row = g_z + (long)r * DP;
        float v0 = row[t];
        s0 += v0; q0 += v0 * v0;
        float v1 = row[t + 128];
        s1 += v1; q1 += v1 * v1;
        if (t + 256 < DD) {
            float v2 = row[t + 256];
            s2 += v2; q2 += v2 * v2;
        }
    }
    atomicAdd(&g_sum[t], s0);       atomicAdd(&g_sq[t], q0);
    atomicAdd(&g_sum[t + 128], s1); atomicAdd(&g_sq[t + 128], q1);
    if (t + 256 < DD) { atomicAdd(&g_sum[t + 256], s2); atomicAdd(&g_sq[t + 256], q2); }
}

// ---------------- BN apply + ReLU ----------------
__global__ void k_bnrelu(const float* __restrict__ gamma, const float* __restrict__ beta,
                         int dst_is_h) {
    int total = NN * DP;
    int stride = gridDim.x * blockDim.x;
    float* out = dst_is_h ? g_h : g_agg;
    const float invn = 1.0f / (float)NN;
    for (int idx = blockIdx.x * blockDim.x + threadIdx.x; idx < total; idx += stride) {
        int c = idx % DP;
        float o = 0.f;
        if (c < DD) {
            float mean = g_sum[c] * invn;
            float var = g_sq[c] * invn - mean * mean;
            float istd = rsqrtf(var + BN_EPS);
            float v = (g_z[idx] - mean) * istd * gamma[c] + beta[c];
            o = fmaxf(v, 0.f);
        }
        out[idx] = o;
    }
}

// ---------------- readout ----------------
__global__ void k_readout(const float* __restrict__ fcW, const float* __restrict__ fcb,
                          float* __restrict__ out) {
    int g = blockIdx.x;
    int c = threadIdx.x;  // 128
    float inv = 1.0f / fmaxf(g_cnt[g], 1.0f);
    float acc = 0.f;
#pragma unroll
    for (int i = 0; i <= LL; ++i) {
        const float* p = g_pooled + ((long)i * NGG + g) * DP;
        const float* W = fcW + (long)i * DD * CC;
        float a = 0.f;
        for (int k = 0; k < DD; ++k)
            a += p[k] * W[k * CC + c];
        acc += inv * a + fcb[i * CC + c];
    }
    out[g * CC + c] = acc;
}

// ---------------- launch ----------------
extern "C" void kernel_launch(void* const* d_in, const int* in_sizes, int n_in,
                              void* d_out, int out_size) {
    const float* x       = (const float*)d_in[0];
    const void*  edg_raw = d_in[1];
    const void*  bat_raw = d_in[2];
    const float* mlp_W1  = (const float*)d_in[3];
    const float* mlp_b1  = (const float*)d_in[4];
    const float* mlp_g1  = (const float*)d_in[5];
    const float* mlp_be1 = (const float*)d_in[6];
    const float* mlp_W2  = (const float*)d_in[7];
    const float* mlp_b2  = (const float*)d_in[8];
    const float* bn_g    = (const float*)d_in[9];
    const float* bn_b    = (const float*)d_in[10];
    const float* fc_W    = (const float*)d_in[11];
    const float* fc_b    = (const float*)d_in[12];
    float* out = (float*)d_out;

    // dtype normalization (int64 vs int32)
    k_zero_flags<<<1, 32>>>();
    k_detect<<<256, 256>>>((const int*)edg_raw, 2 * EE, 0);
    k_detect<<<64, 256>>>((const int*)bat_raw, NN, 1);
    k_convert_edge<<<(2 * EE + 255) / 256, 256>>>(edg_raw);
    k_convert_batch<<<(NN + 255) / 256, 256>>>(bat_raw);

    // param staging
    k_padW<<<1024, 256>>>(mlp_W1, mlp_W2);
    k_padB<<<(2 * LL * DP + 255) / 256, 256>>>(mlp_b1, mlp_b2);
    k_init_h<<<2048, 256>>>(x);
    k_zero_pool<<<1024, 256>>>();
    k_counts<<<(NN + 255) / 256, 256>>>();
    k_pool<<<(NN * 32 + 255) / 256, 256>>>(0);

    dim3 ggrid((DP + GBN - 1) / GBN, (NN + GBM - 1) / GBM);
    for (int i = 0; i < LL; ++i) {
        k_copy<<<2048, 256>>>();
        k_scatter<<<(EE * 32 + 255) / 256, 256>>>();
        k_gemm<<<ggrid, 256>>>(0, i);
        k_zero_stats<<<1, DP>>>();
        k_colstats<<<(NN + 127) / 128, 128>>>();
        k_bnrelu<<<2048, 256>>>(mlp_g1 + i * DD, mlp_be1 + i * DD, 0);
        k_gemm<<<ggrid, 256>>>(1, i);
        k_zero_stats<<<1, DP>>>();
        k_colstats<<<(NN + 127) / 128, 128>>>();
        k_bnrelu<<<2048, 256>>>(bn_g + i * DD, bn_b + i * DD, 1);
        k_pool<<<(NN * 32 + 255) / 256, 256>>>(i + 1);
    }
    k_readout<<<NGG, CC>>>(fc_W, fc_b, out);
}

// round 3
// speedup vs baseline: 1.9813x; 1.9813x over previous
#include <cuda_runtime.h>
#include <cuda_bf16.h>
#include <cstdint>

#define NN 50000
#define EE 400000
#define DD 300
#define DP 320      // padded feature dim (multiple of 32 for BK)
#define LL 5
#define CC 128
#define NGG 256
#define BN_EPS 1e-5f

// ---------------- device scratch (no allocs allowed) ----------------
__device__ float g_h[NN * DP];        // current node features (pad cols = 0)
__device__ float g_agg[NN * DP];      // h + aggregated neighbors / post-BN1 activations
__device__ float g_z[NN * DP];        // GEMM outputs
__device__ float g_W[2 * LL * DP * DP];  // padded weights: [which][layer][DP][DP]
__device__ float g_bias[2 * LL * DP];    // padded biases
__device__ float g_pooled[(LL + 1) * NGG * DP];
__device__ float g_cnt[NGG];
__device__ float g_sum[DP];
__device__ float g_sq[DP];
__device__ int   g_edge[2 * EE];      // src[EE], dst[EE] as int32
__device__ int   g_batch[NN];
__device__ int   g_flag[2];           // 1 => raw data is int32, 0 => int64

// ---------------- small utility kernels ----------------
__global__ void k_zero_flags() {
    if (threadIdx.x < 2) g_flag[threadIdx.x] = 0;
}

__global__ void k_detect(const int* __restrict__ raw, int nwords, int slot) {
    int stride = gridDim.x * blockDim.x;
    for (int i = blockIdx.x * blockDim.x + threadIdx.x; 2 * i + 1 < nwords; i += stride) {
        if (raw[2 * i + 1] != 0) g_flag[slot] = 1;  // benign race
    }
}

__global__ void k_convert_edge(const void* __restrict__ raw) {
    int i = blockIdx.x * blockDim.x + threadIdx.x;
    if (i >= 2 * EE) return;
    if (g_flag[0]) g_edge[i] = ((const int*)raw)[i];
    else           g_edge[i] = (int)((const long long*)raw)[i];
}

__global__ void k_convert_batch(const void* __restrict__ raw) {
    int i = blockIdx.x * blockDim.x + threadIdx.x;
    if (i >= NN) return;
    if (g_flag[1]) g_batch[i] = ((const int*)raw)[i];
    else           g_batch[i] = (int)((const long long*)raw)[i];
}

__global__ void k_padW(const float* __restrict__ W1, const float* __restrict__ W2) {
    int total = 2 * LL * DP * DP;
    int stride = gridDim.x * blockDim.x;
    for (int idx = blockIdx.x * blockDim.x + threadIdx.x; idx < total; idx += stride) {
        int c = idx % DP;
        int r = (idx / DP) % DP;
        int l = (idx / (DP * DP)) % LL;
        int w = idx / (DP * DP * LL);
        float v = 0.f;
        if (r < DD && c < DD) {
            const float* W = w ? W2 : W1;
            v = W[(l * DD + r) * DD + c];
        }
        g_W[idx] = v;
    }
}

__global__ void k_padB(const float* __restrict__ b1, const float* __restrict__ b2) {
    int total = 2 * LL * DP;
    int idx = blockIdx.x * blockDim.x + threadIdx.x;
    if (idx >= total) return;
    int c = idx % DP;
    int l = (idx / DP) % LL;
    int w = idx / (DP * LL);
    float v = 0.f;
    if (c < DD) v = (w ? b2 : b1)[l * DD + c];
    g_bias[idx] = v;
}

__global__ void k_init_h(const float* __restrict__ x) {
    int total = NN * DP;
    int stride = gridDim.x * blockDim.x;
    for (int idx = blockIdx.x * blockDim.x + threadIdx.x; idx < total; idx += stride) {
        int c = idx % DP;
        int n = idx / DP;
        g_h[idx] = (c < DD) ? x[n * DD + c] : 0.f;
    }
}

__global__ void k_zero_pool() {
    int total = (LL + 1) * NGG * DP;
    int stride = gridDim.x * blockDim.x;
    for (int idx = blockIdx.x * blockDim.x + threadIdx.x; idx < total; idx += stride) {
        g_pooled[idx] = 0.f;
        if (idx < NGG) g_cnt[idx] = 0.f;
    }
}

__global__ void k_zero_stats() {
    int i = threadIdx.x;
    if (i < DP) { g_sum[i] = 0.f; g_sq[i] = 0.f; }
}

__global__ void k_counts() {
    int i = blockIdx.x * blockDim.x + threadIdx.x;
    if (i < NN) atomicAdd(&g_cnt[g_batch[i]], 1.0f);
}

__global__ void k_copy() {
    int total = NN * DP / 4;
    int stride = gridDim.x * blockDim.x;
    const float4* s = (const float4*)g_h;
    float4* d = (float4*)g_agg;
    for (int i = blockIdx.x * blockDim.x + threadIdx.x; i < total; i += stride)
        d[i] = s[i];
}

// One warp per edge: g_agg[dst] += g_h[src], vector float4 atomics
__global__ void k_scatter() {
    int warp = (blockIdx.x * blockDim.x + threadIdx.x) >> 5;
    int lane = threadIdx.x & 31;
    if (warp >= EE) return;
    int s = g_edge[warp];
    int t = g_edge[EE + warp];
    const float4* srow = (const float4*)(g_h + (long)s * DP);
    float4* drow = (float4*)(g_agg + (long)t * DP);
#pragma unroll 3
    for (int c = lane; c < DD / 4; c += 32) {
        float4 v = srow[c];
        atomicAdd(&drow[c], v);
    }
}

// One warp per node: g_pooled[depth][batch[n]] += g_h[n]
__global__ void k_pool(int depth) {
    int warp = (blockIdx.x * blockDim.x + threadIdx.x) >> 5;
    int lane = threadIdx.x & 31;
    if (warp >= NN) return;
    int g = g_batch[warp];
    const float4* srow = (const float4*)(g_h + (long)warp * DP);
    float4* drow = (float4*)(g_pooled + ((long)depth * NGG + g) * DP);
#pragma unroll 3
    for (int c = lane; c < DD / 4; c += 32) {
        float4 v = srow[c];
        atomicAdd(&drow[c], v);
    }
}

// ---------------- TF32 tensor-core GEMM: g_z = g_agg @ W + bias ----------------
// Block tile 128x128, BK=32, 8 warps (2x4), warp tile 64x32 = 4x4 m16n8k8 frags.
// cp.async double-buffered. Smem strides 36/136 -> conflict-free fragment LDS.
#define BKC 32
#define ASTRIDE 36
#define BSTRIDE 136
#define ATILE (128 * ASTRIDE)      // 4608 floats
#define BTILE (BKC * BSTRIDE)      // 4352 floats
#define BUFSZ (ATILE + BTILE)      // 8960 floats
#define GEMM_SMEM (2 * BUFSZ * 4)  // 71680 bytes

__device__ __forceinline__ void cpa16(uint32_t dst, const void* src, bool pred) {
    int sz = pred ? 16 : 0;
    asm volatile("cp.async.cg.shared.global [%0], [%1], 16, %2;\n"
                 :: "r"(dst), "l"(src), "r"(sz));
}

__global__ void __launch_bounds__(256) k_gemm(int which, int layer) {
    extern __shared__ float sm[];
    const float* __restrict__ Bw = g_W + ((size_t)which * LL + layer) * DP * DP;
    const float* __restrict__ bias = g_bias + ((size_t)which * LL + layer) * DP;
    const int bm = blockIdx.y * 128;
    const int bn = blockIdx.x * 128;
    const int tid = threadIdx.x;
    const int lane = tid & 31, wid = tid >> 5;
    const int wm = (wid & 1) << 6;   // 0 / 64
    const int wn = (wid >> 1) << 5;  // 0/32/64/96
    const int gid = lane >> 2, tk = lane & 3;

    float c[4][4][4];
#pragma unroll
    for (int i = 0; i < 4; i++)
#pragma unroll
        for (int j = 0; j < 4; j++)
#pragma unroll
            for (int f = 0; f < 4; f++) c[i][j][f] = 0.f;

    const int ar = tid >> 3;         // 0..31  (A row within 32-row pass)
    const int av = (tid & 7) << 2;   // 0..28  (A col, float4)
    const int br = tid >> 5;         // 0..7   (B row within 8-row pass)
    const int bv = (tid & 31) << 2;  // 0..124 (B col, float4)
    const bool bvalid = (bn + bv) < DP;

    uint32_t smb = (uint32_t)__cvta_generic_to_shared(sm);

    // prologue: issue chunk 0 into buffer 0
#pragma unroll
    for (int p = 0; p < 4; p++) {
        int gr = bm + ar + p * 32;
        const float* asrc = g_agg + (size_t)(gr < NN ? gr : 0) * DP + av;
        cpa16(smb + (uint32_t)(((ar + p * 32) * ASTRIDE + av) * 4), asrc, gr < NN);
        int kr = br + p * 8;
        const float* bsrc = Bw + (size_t)kr * DP + (bvalid ? bn + bv : 0);
        cpa16(smb + (uint32_t)((ATILE + kr * BSTRIDE + bv) * 4), bsrc, bvalid);
    }
    asm volatile("cp.async.commit_group;\n");

    int buf = 0;
#pragma unroll 1
    for (int k0 = 0; k0 < DP; k0 += BKC) {
        if (k0 + BKC < DP) {
            int nb = buf ^ 1;
            int k1 = k0 + BKC;
#pragma unroll
            for (int p = 0; p < 4; p++) {
                int gr = bm + ar + p * 32;
                const float* asrc = g_agg + (size_t)(gr < NN ? gr : 0) * DP + k1 + av;
                cpa16(smb + (uint32_t)((nb * BUFSZ + (ar + p * 32) * ASTRIDE + av) * 4),
                      asrc, gr < NN);
                int kr = k1 + br + p * 8;
                const float* bsrc = Bw + (size_t)kr * DP + (bvalid ? bn + bv : 0);
                cpa16(smb + (uint32_t)((nb * BUFSZ + ATILE + (br + p * 8) * BSTRIDE + bv) * 4),
                      bsrc, bvalid);
            }
            asm volatile("cp.async.commit_group;\n");
            asm volatile("cp.async.wait_group 1;\n");
        } else {
            asm volatile("cp.async.wait_group 0;\n");
        }
        __syncthreads();
        const float* As = sm + buf * BUFSZ;
        const float* Bs = As + ATILE;
#pragma unroll
        for (int ks = 0; ks < BKC; ks += 8) {
            uint32_t a[4][4], b[4][2];
#pragma unroll
            for (int mt = 0; mt < 4; mt++) {
                const float* ap = As + (wm + mt * 16 + gid) * ASTRIDE + ks + tk;
                a[mt][0] = __float_as_uint(ap[0]);
                a[mt][1] = __float_as_uint(ap[8 * ASTRIDE]);
                a[mt][2] = __float_as_uint(ap[4]);
                a[mt][3] = __float_as_uint(ap[8 * ASTRIDE + 4]);
            }
#pragma unroll
            for (int nt = 0; nt < 4; nt++) {
                const float* bp = Bs + (ks + tk) * BSTRIDE + wn + nt * 8 + gid;
                b[nt][0] = __float_as_uint(bp[0]);
                b[nt][1] = __float_as_uint(bp[4 * BSTRIDE]);
            }
#pragma unroll
            for (int mt = 0; mt < 4; mt++)
#pragma unroll
                for (int nt = 0; nt < 4; nt++)
                    asm volatile(
                        "mma.sync.aligned.m16n8k8.row.col.f32.tf32.tf32.f32 "
                        "{%0,%1,%2,%3}, {%4,%5,%6,%7}, {%8,%9}, {%0,%1,%2,%3};\n"
                        : "+f"(c[mt][nt][0]), "+f"(c[mt][nt][1]),
                          "+f"(c[mt][nt][2]), "+f"(c[mt][nt][3])
                        : "r"(a[mt][0]), "r"(a[mt][1]), "r"(a[mt][2]), "r"(a[mt][3]),
                          "r"(b[nt][0]), "r"(b[nt][1]));
        }
        __syncthreads();
        buf ^= 1;
    }

    // epilogue: + bias
#pragma unroll
    for (int mt = 0; mt < 4; mt++) {
        int r0 = bm + wm + mt * 16 + gid;
#pragma unroll
        for (int nt = 0; nt < 4; nt++) {
            int c0 = bn + wn + nt * 8 + 2 * tk;
            if (c0 < DP) {
                float b0 = bias[c0], b1 = bias[c0 + 1];
                if (r0 < NN) {
                    float2 v = make_float2(c[mt][nt][0] + b0, c[mt][nt][1] + b1);
                    *(float2*)(g_z + (size_t)r0 * DP + c0) = v;
                }
                if (r0 + 8 < NN) {
                    float2 v = make_float2(c[mt][nt][2] + b0, c[mt][nt][3] + b1);
                    *(float2*)(g_z + (size_t)(r0 + 8) * DP + c0) = v;
                }
            }
        }
    }
}

// ---------------- BN stats: per-column sum & sumsq over g_z ----------------
__global__ void k_colstats() {
    int t = threadIdx.x;  // 128
    int r0 = blockIdx.x * 128;
    int rend = min(r0 + 128, NN);
    float s0 = 0.f, q0 = 0.f, s1 = 0.f, q1 = 0.f, s2 = 0.f, q2 = 0.f;
    for (int r = r0; r < rend; ++r) {
        const float* row = g_z + (long)r * DP;
        float v0 = row[t];
        s0 += v0; q0 += v0 * v0;
        float v1 = row[t + 128];
        s1 += v1; q1 += v1 * v1;
        if (t + 256 < DD) {
            float v2 = row[t + 256];
            s2 += v2; q2 += v2 * v2;
        }
    }
    atomicAdd(&g_sum[t], s0);       atomicAdd(&g_sq[t], q0);
    atomicAdd(&g_sum[t + 128], s1); atomicAdd(&g_sq[t + 128], q1);
    if (t + 256 < DD) { atomicAdd(&g_sum[t + 256], s2); atomicAdd(&g_sq[t + 256], q2); }
}

// ---------------- BN apply + ReLU ----------------
__global__ void k_bnrelu(const float* __restrict__ gamma, const float* __restrict__ beta,
                         int dst_is_h) {
    int total = NN * DP;
    int stride = gridDim.x * blockDim.x;
    float* out = dst_is_h ? g_h : g_agg;
    const float invn = 1.0f / (float)NN;
    for (int idx = blockIdx.x * blockDim.x + threadIdx.x; idx < total; idx += stride) {
        int c = idx % DP;
        float o = 0.f;
        if (c < DD) {
            float mean = g_sum[c] * invn;
            float var = g_sq[c] * invn - mean * mean;
            float istd = rsqrtf(var + BN_EPS);
            float v = (g_z[idx] - mean) * istd * gamma[c] + beta[c];
            o = fmaxf(v, 0.f);
        }
        out[idx] = o;
    }
}

// ---------------- readout ----------------
__global__ void k_readout(const float* __restrict__ fcW, const float* __restrict__ fcb,
                          float* __restrict__ out) {
    int g = blockIdx.x;
    int c = threadIdx.x;  // 128
    float inv = 1.0f / fmaxf(g_cnt[g], 1.0f);
    float acc = 0.f;
#pragma unroll
    for (int i = 0; i <= LL; ++i) {
        const float* p = g_pooled + ((long)i * NGG + g) * DP;
        const float* W = fcW + (long)i * DD * CC;
        float a = 0.f;
        for (int k = 0; k < DD; ++k)
            a += p[k] * W[k * CC + c];
        acc += inv * a + fcb[i * CC + c];
    }
    out[g * CC + c] = acc;
}

// ---------------- launch ----------------
extern "C" void kernel_launch(void* const* d_in, const int* in_sizes, int n_in,
                              void* d_out, int out_size) {
    const float* x       = (const float*)d_in[0];
    const void*  edg_raw = d_in[1];
    const void*  bat_raw = d_in[2];
    const float* mlp_W1  = (const float*)d_in[3];
    const float* mlp_b1  = (const float*)d_in[4];
    const float* mlp_g1  = (const float*)d_in[5];
    const float* mlp_be1 = (const float*)d_in[6];
    const float* mlp_W2  = (const float*)d_in[7];
    const float* mlp_b2  = (const float*)d_in[8];
    const float* bn_g    = (const float*)d_in[9];
    const float* bn_b    = (const float*)d_in[10];
    const float* fc_W    = (const float*)d_in[11];
    const float* fc_b    = (const float*)d_in[12];
    float* out = (float*)d_out;

    static bool done = false;
    if (!done) {
        cudaFuncSetAttribute(k_gemm, cudaFuncAttributeMaxDynamicSharedMemorySize, GEMM_SMEM);
        done = true;
    }

    // dtype normalization (int64 vs int32)
    k_zero_flags<<<1, 32>>>();
    k_detect<<<256, 256>>>((const int*)edg_raw, 2 * EE, 0);
    k_detect<<<64, 256>>>((const int*)bat_raw, NN, 1);
    k_convert_edge<<<(2 * EE + 255) / 256, 256>>>(edg_raw);
    k_convert_batch<<<(NN + 255) / 256, 256>>>(bat_raw);

    // param staging
    k_padW<<<1024, 256>>>(mlp_W1, mlp_W2);
    k_padB<<<(2 * LL * DP + 255) / 256, 256>>>(mlp_b1, mlp_b2);
    k_init_h<<<2048, 256>>>(x);
    k_zero_pool<<<1024, 256>>>();
    k_counts<<<(NN + 255) / 256, 256>>>();
    k_pool<<<(NN * 32 + 255) / 256, 256>>>(0);

    dim3 ggrid((DP + 127) / 128, (NN + 127) / 128);
    for (int i = 0; i < LL; ++i) {
        k_copy<<<2048, 256>>>();
        k_scatter<<<(EE * 32 + 255) / 256, 256>>>();
        k_gemm<<<ggrid, 256, GEMM_SMEM>>>(0, i);
        k_zero_stats<<<1, DP>>>();
        k_colstats<<<(NN + 127) / 128, 128>>>();
        k_bnrelu<<<2048, 256>>>(mlp_g1 + i * DD, mlp_be1 + i * DD, 0);
        k_gemm<<<ggrid, 256, GEMM_SMEM>>>(1, i);
        k_zero_stats<<<1, DP>>>();
        k_colstats<<<(NN + 127) / 128, 128>>>();
        k_bnrelu<<<2048, 256>>>(bn_g + i * DD, bn_b + i * DD, 1);
        k_pool<<<(NN * 32 + 255) / 256, 256>>>(i + 1);
    }
    k_readout<<<NGG, CC>>>(fc_W, fc_b, out);
}

// round 8
// speedup vs baseline: 2.5825x; 1.3035x over previous
#include <cuda_runtime.h>
#include <cuda_bf16.h>
#include <cstdint>

#define NN 50000
#define EE 400000
#define DD 300
#define DP 320      // padded feature dim (multiple of 32 for BK)
#define LL 5
#define CC 128
#define NGG 256
#define BN_EPS 1e-5f
#define NSLOT (2 * LL)

// ---------------- device scratch (no allocs allowed) ----------------
__device__ float g_h[NN * DP];        // current node features
__device__ float g_agg[NN * DP];      // h + aggregated neighbors (scatter target / GEMM1 A)
__device__ float g_z[NN * DP];        // GEMM1 output (pre-BN1)
__device__ float g_zb[NN * DP];       // GEMM2 output (pre-BN2)
__device__ float g_W[2 * LL * DP * DP];
__device__ float g_bias[2 * LL * DP];
__device__ float g_pooled[(LL + 1) * NGG * DP];
__device__ float g_cnt[NGG];
__device__ float g_sum[NSLOT * DP];
__device__ float g_sq[NSLOT * DP];
__device__ float g_scale[NSLOT * DP];
__device__ float g_shift[NSLOT * DP];
__device__ int   g_edge[2 * EE];
__device__ int   g_batch[NN];
__device__ int   g_flag[2];

// ---------------- setup kernels ----------------
__global__ void k_zero_flags() {
    if (threadIdx.x < 2) g_flag[threadIdx.x] = 0;
}

__global__ void k_detect(const int* __restrict__ raw, int nwords, int slot) {
    int stride = gridDim.x * blockDim.x;
    for (int i = blockIdx.x * blockDim.x + threadIdx.x; 2 * i + 1 < nwords; i += stride) {
        if (raw[2 * i + 1] != 0) g_flag[slot] = 1;  // benign race
    }
}

__global__ void k_convert_edge(const void* __restrict__ raw) {
    int i = blockIdx.x * blockDim.x + threadIdx.x;
    if (i >= 2 * EE) return;
    if (g_flag[0]) g_edge[i] = ((const int*)raw)[i];
    else           g_edge[i] = (int)((const long long*)raw)[i];
}

__global__ void k_convert_batch(const void* __restrict__ raw) {
    int i = blockIdx.x * blockDim.x + threadIdx.x;
    if (i >= NN) return;
    if (g_flag[1]) g_batch[i] = ((const int*)raw)[i];
    else           g_batch[i] = (int)((const long long*)raw)[i];
}

__global__ void k_padW(const float* __restrict__ W1, const float* __restrict__ W2) {
    int total = 2 * LL * DP * DP;
    int stride = gridDim.x * blockDim.x;
    for (int idx = blockIdx.x * blockDim.x + threadIdx.x; idx < total; idx += stride) {
        int c = idx % DP;
        int r = (idx / DP) % DP;
        int l = (idx / (DP * DP)) % LL;
        int w = idx / (DP * DP * LL);
        float v = 0.f;
        if (r < DD && c < DD) {
            const float* W = w ? W2 : W1;
            v = W[(l * DD + r) * DD + c];
        }
        g_W[idx] = v;
    }
}

__global__ void k_padB(const float* __restrict__ b1, const float* __restrict__ b2) {
    int total = 2 * LL * DP;
    int idx = blockIdx.x * blockDim.x + threadIdx.x;
    if (idx >= total) return;
    int c = idx % DP;
    int l = (idx / DP) % LL;
    int w = idx / (DP * LL);
    float v = 0.f;
    if (c < DD) v = (w ? b2 : b1)[l * DD + c];
    g_bias[idx] = v;
}

__global__ void k_zero_pool() {
    int total = (LL + 1) * NGG * DP;
    int stride = gridDim.x * blockDim.x;
    for (int idx = blockIdx.x * blockDim.x + threadIdx.x; idx < total; idx += stride) {
        g_pooled[idx] = 0.f;
        if (idx < NGG) g_cnt[idx] = 0.f;
    }
}

__global__ void k_zero_stats() {
    int idx = blockIdx.x * blockDim.x + threadIdx.x;
    if (idx < NSLOT * DP) { g_sum[idx] = 0.f; g_sq[idx] = 0.f; }
}

// Warp-per-row: x -> g_h & g_agg (padded), pool depth 0, counts.
__global__ void k_initfuse(const float* __restrict__ x) {
    int row = (blockIdx.x * blockDim.x + threadIdx.x) >> 5;
    int lane = threadIdx.x & 31;
    if (row >= NN) return;
    int g = g_batch[row];
    const float4* xs = (const float4*)(x + (size_t)row * DD);
    float4* ph = (float4*)(g_h + (size_t)row * DP);
    float4* pa = (float4*)(g_agg + (size_t)row * DP);
    float4* pp = (float4*)(g_pooled + (size_t)g * DP);
#pragma unroll 3
    for (int c4 = lane; c4 < DP / 4; c4 += 32) {
        float4 v = (c4 < DD / 4) ? xs[c4] : make_float4(0.f, 0.f, 0.f, 0.f);
        ph[c4] = v;
        pa[c4] = v;
        if (c4 < DD / 4) atomicAdd(&pp[c4], v);
    }
    if (lane == 0) atomicAdd(&g_cnt[g], 1.0f);
}

// One warp per edge: g_agg[dst] += g_h[src]
__global__ void k_scatter() {
    int warp = (blockIdx.x * blockDim.x + threadIdx.x) >> 5;
    int lane = threadIdx.x & 31;
    if (warp >= EE) return;
    int s = g_edge[warp];
    int t = g_edge[EE + warp];
    const float4* srow = (const float4*)(g_h + (size_t)s * DP);
    float4* drow = (float4*)(g_agg + (size_t)t * DP);
#pragma unroll 3
    for (int c = lane; c < DD / 4; c += 32) {
        float4 v = srow[c];
        atomicAdd(&drow[c], v);
    }
}

// stats -> per-column scale/shift (one block of DP threads)
__global__ void k_bnprep(int slot, const float* __restrict__ gamma,
                         const float* __restrict__ beta) {
    int c = threadIdx.x;
    if (c >= DP) return;
    float sc = 0.f, sh = 0.f;
    if (c < DD) {
        const float invn = 1.0f / (float)NN;
        float mean = g_sum[slot * DP + c] * invn;
        float var = g_sq[slot * DP + c] * invn - mean * mean;
        float istd = rsqrtf(var + BN_EPS);
        sc = istd * gamma[c];
        sh = beta[c] - mean * sc;
    }
    g_scale[slot * DP + c] = sc;
    g_shift[slot * DP + c] = sh;
}

// Warp-per-row: h = relu(bn2(zb)), write g_h & g_agg, pool into depth.
__global__ void k_bnfuse(int slot, int depth) {
    int row = (blockIdx.x * blockDim.x + threadIdx.x) >> 5;
    int lane = threadIdx.x & 31;
    if (row >= NN) return;
    int g = g_batch[row];
    const float* scl = g_scale + slot * DP;
    const float* shf = g_shift + slot * DP;
    const float4* zs = (const float4*)(g_zb + (size_t)row * DP);
    float4* ph = (float4*)(g_h + (size_t)row * DP);
    float4* pa = (float4*)(g_agg + (size_t)row * DP);
    float4* pp = (float4*)(g_pooled + ((size_t)depth * NGG + g) * DP);
#pragma unroll 3
    for (int c4 = lane; c4 < DP / 4; c4 += 32) {
        int c = c4 * 4;
        float4 v = zs[c4];
        v.x = fmaxf(fmaf(v.x, scl[c + 0], shf[c + 0]), 0.f);
        v.y = fmaxf(fmaf(v.y, scl[c + 1], shf[c + 1]), 0.f);
        v.z = fmaxf(fmaf(v.z, scl[c + 2], shf[c + 2]), 0.f);
        v.w = fmaxf(fmaf(v.w, scl[c + 3], shf[c + 3]), 0.f);
        ph[c4] = v;
        pa[c4] = v;
        if (c4 < DD / 4) atomicAdd(&pp[c4], v);
    }
}

// ---------------- TF32 tensor-core GEMM, stats fused in epilogue ----------------
// asel: 0 -> A = g_agg, 1 -> A = g_z.  osel: 0 -> Out = g_z, 1 -> Out = g_zb.
// FUSE=1: A transformed v = relu(v*scale+shift) on load (BN applied on the fly).
#define BKC 32
#define ASTRIDE 36
#define BSTRIDE 136
#define ATILE (128 * ASTRIDE)
#define BTILE (BKC * BSTRIDE)
#define BUFSZ (ATILE + BTILE)
#define GEMM_SMEM (2 * BUFSZ * 4)  // 71680 bytes

__device__ __forceinline__ void cpa16(uint32_t dst, const void* src, bool pred) {
    int sz = pred ? 16 : 0;
    asm volatile("cp.async.cg.shared.global [%0], [%1], 16, %2;\n"
                 :: "r"(dst), "l"(src), "r"(sz));
}

template <int FUSE>
__global__ void __launch_bounds__(256) k_gemm(int asel, int osel,
                                              int which, int layer,
                                              int slot_in, int slot_out) {
    extern __shared__ float sm[];
    const float* __restrict__ Asrc = asel ? g_z : g_agg;   // device-side symbol resolve
    float* __restrict__ Out = osel ? g_zb : g_z;
    const float* __restrict__ Bw = g_W + ((size_t)which * LL + layer) * DP * DP;
    const float* __restrict__ bias = g_bias + ((size_t)which * LL + layer) * DP;
    const float* __restrict__ scl = g_scale + (size_t)slot_in * DP;
    const float* __restrict__ shf = g_shift + (size_t)slot_in * DP;
    const int bm = blockIdx.y * 128;
    const int bn = blockIdx.x * 128;
    const int tid = threadIdx.x;
    const int lane = tid & 31, wid = tid >> 5;
    const int wm = (wid & 1) << 6;
    const int wn = (wid >> 1) << 5;
    const int gid = lane >> 2, tk = lane & 3;

    float c[4][4][4];
#pragma unroll
    for (int i = 0; i < 4; i++)
#pragma unroll
        for (int j = 0; j < 4; j++)
#pragma unroll
            for (int f = 0; f < 4; f++) c[i][j][f] = 0.f;

    const int ar = tid >> 3;         // 0..31
    const int av = (tid & 7) << 2;   // 0..28
    const int br = tid >> 5;         // 0..7
    const int bv = (tid & 31) << 2;  // 0..124
    const bool bvalid = (bn + bv) < DP;

    uint32_t smb = (uint32_t)__cvta_generic_to_shared(sm);

    // ---------- prologue ----------
    if (FUSE) {
        float4 areg[4];
#pragma unroll
        for (int p = 0; p < 4; p++) {
            int gr = bm + ar + p * 32;
            areg[p] = (gr < NN) ? *(const float4*)(Asrc + (size_t)gr * DP + av)
                                : make_float4(0.f, 0.f, 0.f, 0.f);
        }
#pragma unroll
        for (int p = 0; p < 4; p++) {
            int kr = br + p * 8;
            const float* bsrc = Bw + (size_t)kr * DP + (bvalid ? bn + bv : 0);
            cpa16(smb + (uint32_t)((ATILE + kr * BSTRIDE + bv) * 4), bsrc, bvalid);
        }
        asm volatile("cp.async.commit_group;\n");
        float sc0 = scl[av], sc1 = scl[av + 1], sc2 = scl[av + 2], sc3 = scl[av + 3];
        float sh0 = shf[av], sh1 = shf[av + 1], sh2 = shf[av + 2], sh3 = shf[av + 3];
#pragma unroll
        for (int p = 0; p < 4; p++) {
            float4 v = areg[p];
            v.x = fmaxf(fmaf(v.x, sc0, sh0), 0.f);
            v.y = fmaxf(fmaf(v.y, sc1, sh1), 0.f);
            v.z = fmaxf(fmaf(v.z, sc2, sh2), 0.f);
            v.w = fmaxf(fmaf(v.w, sc3, sh3), 0.f);
            float* d = sm + (ar + p * 32) * ASTRIDE + av;
            d[0] = v.x; d[1] = v.y; d[2] = v.z; d[3] = v.w;
        }
    } else {
#pragma unroll
        for (int p = 0; p < 4; p++) {
            int gr = bm + ar + p * 32;
            const float* asrc = Asrc + (size_t)(gr < NN ? gr : 0) * DP + av;
            cpa16(smb + (uint32_t)(((ar + p * 32) * ASTRIDE + av) * 4), asrc, gr < NN);
            int kr = br + p * 8;
            const float* bsrc = Bw + (size_t)kr * DP + (bvalid ? bn + bv : 0);
            cpa16(smb + (uint32_t)((ATILE + kr * BSTRIDE + bv) * 4), bsrc, bvalid);
        }
        asm volatile("cp.async.commit_group;\n");
    }

    int buf = 0;
#pragma unroll 1
    for (int k0 = 0; k0 < DP; k0 += BKC) {
        const bool has = (k0 + BKC < DP);
        float4 areg[4];
        float sc0, sc1, sc2, sc3, sh0, sh1, sh2, sh3;
        if (has) {
            int nb = buf ^ 1;
            int k1 = k0 + BKC;
            if (FUSE) {
#pragma unroll
                for (int p = 0; p < 4; p++) {
                    int gr = bm + ar + p * 32;
                    areg[p] = (gr < NN)
                        ? *(const float4*)(Asrc + (size_t)gr * DP + k1 + av)
                        : make_float4(0.f, 0.f, 0.f, 0.f);
                }
                sc0 = scl[k1 + av]; sc1 = scl[k1 + av + 1];
                sc2 = scl[k1 + av + 2]; sc3 = scl[k1 + av + 3];
                sh0 = shf[k1 + av]; sh1 = shf[k1 + av + 1];
                sh2 = shf[k1 + av + 2]; sh3 = shf[k1 + av + 3];
#pragma unroll
                for (int p = 0; p < 4; p++) {
                    int kr = k1 + br + p * 8;
                    const float* bsrc = Bw + (size_t)kr * DP + (bvalid ? bn + bv : 0);
                    cpa16(smb + (uint32_t)((nb * BUFSZ + ATILE + (br + p * 8) * BSTRIDE + bv) * 4),
                          bsrc, bvalid);
                }
            } else {
#pragma unroll
                for (int p = 0; p < 4; p++) {
                    int gr = bm + ar + p * 32;
                    const float* asrc = Asrc + (size_t)(gr < NN ? gr : 0) * DP + k1 + av;
                    cpa16(smb + (uint32_t)((nb * BUFSZ + (ar + p * 32) * ASTRIDE + av) * 4),
                          asrc, gr < NN);
                    int kr = k1 + br + p * 8;
                    const float* bsrc = Bw + (size_t)kr * DP + (bvalid ? bn + bv : 0);
                    cpa16(smb + (uint32_t)((nb * BUFSZ + ATILE + (br + p * 8) * BSTRIDE + bv) * 4),
                          bsrc, bvalid);
                }
            }
            asm volatile("cp.async.commit_group;\n");
            asm volatile("cp.async.wait_group 1;\n");
        } else {
            asm volatile("cp.async.wait_group 0;\n");
        }
        __syncthreads();
        const float* As = sm + buf * BUFSZ;
        const float* Bs = As + ATILE;
#pragma unroll
        for (int ks = 0; ks < BKC; ks += 8) {
            uint32_t a[4][4], b[4][2];
#pragma unroll
            for (int mt = 0; mt < 4; mt++) {
                const float* ap = As + (wm + mt * 16 + gid) * ASTRIDE + ks + tk;
                a[mt][0] = __float_as_uint(ap[0]);
                a[mt][1] = __float_as_uint(ap[8 * ASTRIDE]);
                a[mt][2] = __float_as_uint(ap[4]);
                a[mt][3] = __float_as_uint(ap[8 * ASTRIDE + 4]);
            }
#pragma unroll
            for (int nt = 0; nt < 4; nt++) {
                const float* bp = Bs + (ks + tk) * BSTRIDE + wn + nt * 8 + gid;
                b[nt][0] = __float_as_uint(bp[0]);
                b[nt][1] = __float_as_uint(bp[4 * BSTRIDE]);
            }
#pragma unroll
            for (int mt = 0; mt < 4; mt++)
#pragma unroll
                for (int nt = 0; nt < 4; nt++)
                    asm volatile(
                        "mma.sync.aligned.m16n8k8.row.col.f32.tf32.tf32.f32 "
                        "{%0,%1,%2,%3}, {%4,%5,%6,%7}, {%8,%9}, {%0,%1,%2,%3};\n"
                        : "+f"(c[mt][nt][0]), "+f"(c[mt][nt][1]),
                          "+f"(c[mt][nt][2]), "+f"(c[mt][nt][3])
                        : "r"(a[mt][0]), "r"(a[mt][1]), "r"(a[mt][2]), "r"(a[mt][3]),
                          "r"(b[nt][0]), "r"(b[nt][1]));
        }
        __syncthreads();
        if (FUSE && has) {
            int nb = buf ^ 1;
#pragma unroll
            for (int p = 0; p < 4; p++) {
                float4 v = areg[p];
                v.x = fmaxf(fmaf(v.x, sc0, sh0), 0.f);
                v.y = fmaxf(fmaf(v.y, sc1, sh1), 0.f);
                v.z = fmaxf(fmaf(v.z, sc2, sh2), 0.f);
                v.w = fmaxf(fmaf(v.w, sc3, sh3), 0.f);
                float* d = sm + nb * BUFSZ + (ar + p * 32) * ASTRIDE + av;
                d[0] = v.x; d[1] = v.y; d[2] = v.z; d[3] = v.w;
            }
        }
        buf ^= 1;
    }

    // ---------- epilogue: store + bias, fused column stats ----------
    float* Sg = g_sum + (size_t)slot_out * DP;
    float* Qg = g_sq + (size_t)slot_out * DP;
#pragma unroll
    for (int nt = 0; nt < 4; nt++) {
        int c0 = bn + wn + nt * 8 + 2 * tk;
        if (c0 >= DP) continue;
        float b0 = bias[c0], b1 = bias[c0 + 1];
        float s0 = 0.f, q0 = 0.f, s1 = 0.f, q1 = 0.f;
#pragma unroll
        for (int mt = 0; mt < 4; mt++) {
            int r0 = bm + wm + mt * 16 + gid;
            float v00 = c[mt][nt][0] + b0, v01 = c[mt][nt][1] + b1;
            float v10 = c[mt][nt][2] + b0, v11 = c[mt][nt][3] + b1;
            if (r0 < NN) {
                *(float2*)(Out + (size_t)r0 * DP + c0) = make_float2(v00, v01);
                s0 += v00; q0 += v00 * v00;
                s1 += v01; q1 += v01 * v01;
            }
            if (r0 + 8 < NN) {
                *(float2*)(Out + (size_t)(r0 + 8) * DP + c0) = make_float2(v10, v11);
                s0 += v10; q0 += v10 * v10;
                s1 += v11; q1 += v11 * v11;
            }
        }
#pragma unroll
        for (int off = 16; off >= 4; off >>= 1) {
            s0 += __shfl_xor_sync(0xffffffffu, s0, off);
            q0 += __shfl_xor_sync(0xffffffffu, q0, off);
            s1 += __shfl_xor_sync(0xffffffffu, s1, off);
            q1 += __shfl_xor_sync(0xffffffffu, q1, off);
        }
        if (gid == 0) {
            atomicAdd(&Sg[c0], s0);
            atomicAdd(&Qg[c0], q0);
            atomicAdd(&Sg[c0 + 1], s1);
            atomicAdd(&Qg[c0 + 1], q1);
        }
    }
}

// ---------------- readout ----------------
__global__ void k_readout(const float* __restrict__ fcW, const float* __restrict__ fcb,
                          float* __restrict__ out) {
    int g = blockIdx.x;
    int c = threadIdx.x;  // 128
    float inv = 1.0f / fmaxf(g_cnt[g], 1.0f);
    float acc = 0.f;
#pragma unroll
    for (int i = 0; i <= LL; ++i) {
        const float* p = g_pooled + ((size_t)i * NGG + g) * DP;
        const float* W = fcW + (size_t)i * DD * CC;
        float a = 0.f;
        for (int k = 0; k < DD; ++k)
            a += p[k] * W[k * CC + c];
        acc += inv * a + fcb[i * CC + c];
    }
    out[g * CC + c] = acc;
}

// ---------------- launch ----------------
extern "C" void kernel_launch(void* const* d_in, const int* in_sizes, int n_in,
                              void* d_out, int out_size) {
    const float* x       = (const float*)d_in[0];
    const void*  edg_raw = d_in[1];
    const void*  bat_raw = d_in[2];
    const float* mlp_W1  = (const float*)d_in[3];
    const float* mlp_b1  = (const float*)d_in[4];
    const float* mlp_g1  = (const float*)d_in[5];
    const float* mlp_be1 = (const float*)d_in[6];
    const float* mlp_W2  = (const float*)d_in[7];
    const float* mlp_b2  = (const float*)d_in[8];
    const float* bn_g    = (const float*)d_in[9];
    const float* bn_b    = (const float*)d_in[10];
    const float* fc_W    = (const float*)d_in[11];
    const float* fc_b    = (const float*)d_in[12];
    float* out = (float*)d_out;

    static bool done = false;
    if (!done) {
        cudaFuncSetAttribute(k_gemm<0>, cudaFuncAttributeMaxDynamicSharedMemorySize, GEMM_SMEM);
        cudaFuncSetAttribute(k_gemm<1>, cudaFuncAttributeMaxDynamicSharedMemorySize, GEMM_SMEM);
        done = true;
    }

    // dtype normalization (int64 vs int32)
    k_zero_flags<<<1, 32>>>();
    k_detect<<<256, 256>>>((const int*)edg_raw, 2 * EE, 0);
    k_detect<<<64, 256>>>((const int*)bat_raw, NN, 1);
    k_convert_edge<<<(2 * EE + 255) / 256, 256>>>(edg_raw);
    k_convert_batch<<<(NN + 255) / 256, 256>>>(bat_raw);

    // param staging + init
    k_padW<<<1024, 256>>>(mlp_W1, mlp_W2);
    k_padB<<<(2 * LL * DP + 255) / 256, 256>>>(mlp_b1, mlp_b2);
    k_zero_pool<<<1024, 256>>>();
    k_zero_stats<<<(NSLOT * DP + 255) / 256, 256>>>();
    k_initfuse<<<(NN * 32 + 255) / 256, 256>>>(x);

    dim3 ggrid((DP + 127) / 128, (NN + 127) / 128);
    for (int i = 0; i < LL; ++i) {
        k_scatter<<<(EE * 32 + 255) / 256, 256>>>();
        // GEMM1: z = agg @ W1 + b1, stats slot 2i
        k_gemm<0><<<ggrid, 256, GEMM_SMEM>>>(0, 0, 0, i, 0, 2 * i);
        k_bnprep<<<1, DP>>>(2 * i, mlp_g1 + i * DD, mlp_be1 + i * DD);
        // GEMM2: zb = relu(bn1(z)) @ W2 + b2, BN fused on A-load, stats slot 2i+1
        k_gemm<1><<<ggrid, 256, GEMM_SMEM>>>(1, 1, 1, i, 2 * i, 2 * i + 1);
        k_bnprep<<<1, DP>>>(2 * i + 1, bn_g + i * DD, bn_b + i * DD);
        // h = relu(bn2(zb)); write h & agg; pool depth i+1
        k_bnfuse<<<(NN * 32 + 255) / 256, 256>>>(2 * i + 1, i + 1);
    }
    k_readout<<<NGG, CC>>>(fc_W, fc_b, out);
}

// round 10
// speedup vs baseline: 3.1927x; 1.2363x over previous
#include <cuda_runtime.h>
#include <cuda_bf16.h>
#include <cstdint>

#define NN 50000
#define EE 400000
#define DD 300
#define DP 320      // padded feature dim (multiple of 32 for BK)
#define LL 5
#define CC 128
#define NGG 256
#define BN_EPS 1e-5f
#define NSLOT (2 * LL)
#define PR 64       // rows per block in fuse kernels

// ---------------- device scratch (no allocs allowed) ----------------
__device__ float g_h[NN * DP];        // current node features
__device__ float g_agg[NN * DP];      // h + aggregated neighbors (GEMM1 A)
__device__ float g_z[NN * DP];        // GEMM1 output (pre-BN1)
__device__ float g_zb[NN * DP];       // GEMM2 output (pre-BN2)
__device__ float g_W[2 * LL * DP * DP];
__device__ float g_bias[2 * LL * DP];
__device__ float g_pooled[(LL + 1) * NGG * DP];
__device__ float g_cnt[NGG];
__device__ float g_sum[NSLOT * DP];
__device__ float g_sq[NSLOT * DP];
__device__ float g_scale[NSLOT * DP];
__device__ float g_shift[NSLOT * DP];
__device__ int   g_edge[2 * EE];
__device__ int   g_batch[NN];
__device__ int   g_flag[2];
__device__ int   g_rowptr[NN + 1];
__device__ int   g_cursor[NN];
__device__ int   g_csrc[EE];

// ---------------- setup kernels ----------------
__global__ void k_zero_flags() {
    if (threadIdx.x < 2) g_flag[threadIdx.x] = 0;
}

__global__ void k_detect(const int* __restrict__ raw, int nwords, int slot) {
    int stride = gridDim.x * blockDim.x;
    for (int i = blockIdx.x * blockDim.x + threadIdx.x; 2 * i + 1 < nwords; i += stride) {
        if (raw[2 * i + 1] != 0) g_flag[slot] = 1;  // benign race
    }
}

__global__ void k_convert_edge(const void* __restrict__ raw) {
    int i = blockIdx.x * blockDim.x + threadIdx.x;
    if (i >= 2 * EE) return;
    if (g_flag[0]) g_edge[i] = ((const int*)raw)[i];
    else           g_edge[i] = (int)((const long long*)raw)[i];
}

__global__ void k_convert_batch(const void* __restrict__ raw) {
    int i = blockIdx.x * blockDim.x + threadIdx.x;
    if (i >= NN) return;
    if (g_flag[1]) g_batch[i] = ((const int*)raw)[i];
    else           g_batch[i] = (int)((const long long*)raw)[i];
}

__global__ void k_padW(const float* __restrict__ W1, const float* __restrict__ W2) {
    int total = 2 * LL * DP * DP;
    int stride = gridDim.x * blockDim.x;
    for (int idx = blockIdx.x * blockDim.x + threadIdx.x; idx < total; idx += stride) {
        int c = idx % DP;
        int r = (idx / DP) % DP;
        int l = (idx / (DP * DP)) % LL;
        int w = idx / (DP * DP * LL);
        float v = 0.f;
        if (r < DD && c < DD) {
            const float* W = w ? W2 : W1;
            v = W[(l * DD + r) * DD + c];
        }
        g_W[idx] = v;
    }
}

__global__ void k_padB(const float* __restrict__ b1, const float* __restrict__ b2) {
    int total = 2 * LL * DP;
    int idx = blockIdx.x * blockDim.x + threadIdx.x;
    if (idx >= total) return;
    int c = idx % DP;
    int l = (idx / DP) % LL;
    int w = idx / (DP * LL);
    float v = 0.f;
    if (c < DD) v = (w ? b2 : b1)[l * DD + c];
    g_bias[idx] = v;
}

__global__ void k_zero_pool() {
    int total = (LL + 1) * NGG * DP;
    int stride = gridDim.x * blockDim.x;
    for (int idx = blockIdx.x * blockDim.x + threadIdx.x; idx < total; idx += stride) {
        g_pooled[idx] = 0.f;
        if (idx < NGG) g_cnt[idx] = 0.f;
    }
}

__global__ void k_zero_stats() {
    int idx = blockIdx.x * blockDim.x + threadIdx.x;
    if (idx < NSLOT * DP) { g_sum[idx] = 0.f; g_sq[idx] = 0.f; }
}

// ---------------- CSR build (once per launch) ----------------
__global__ void k_zero_deg() {
    int i = blockIdx.x * blockDim.x + threadIdx.x;
    if (i <= NN) g_rowptr[i] = 0;
}

__global__ void k_hist() {
    int i = blockIdx.x * blockDim.x + threadIdx.x;
    if (i < EE) atomicAdd(&g_rowptr[g_edge[EE + i] + 1], 1);
}

// single block, 1024 threads: inclusive prefix over g_rowptr[1..NN]
__global__ void k_scan() {
    __shared__ int ssum[1024];
    const int CH = (NN + 1023) / 1024;  // 49
    int t = threadIdx.x;
    int beg = t * CH, end = min(beg + CH, NN);
    int s = 0;
    for (int i = beg; i < end; i++) s += g_rowptr[i + 1];
    ssum[t] = s;
    __syncthreads();
    for (int off = 1; off < 1024; off <<= 1) {
        int v = (t >= off) ? ssum[t - off] : 0;
        __syncthreads();
        ssum[t] += v;
        __syncthreads();
    }
    int run = (t > 0) ? ssum[t - 1] : 0;
    for (int i = beg; i < end; i++) {
        run += g_rowptr[i + 1];
        g_rowptr[i + 1] = run;
    }
    if (t == 0) g_rowptr[0] = 0;
}

__global__ void k_copycur() {
    int i = blockIdx.x * blockDim.x + threadIdx.x;
    if (i < NN) g_cursor[i] = g_rowptr[i];
}

__global__ void k_place() {
    int i = blockIdx.x * blockDim.x + threadIdx.x;
    if (i >= EE) return;
    int dst = g_edge[EE + i];
    int pos = atomicAdd(&g_cursor[dst], 1);
    g_csrc[pos] = g_edge[i];
}

// ---------------- aggregation: warp per node, no atomics ----------------
// agg[n] = h[n] + sum_{e in csr row n} h[csrc[e]]
__global__ void k_aggregate() {
    int n = (blockIdx.x * blockDim.x + threadIdx.x) >> 5;
    int lane = threadIdx.x & 31;
    if (n >= NN) return;
    int beg = g_rowptr[n], end = g_rowptr[n + 1];
    const float4* hb = (const float4*)g_h;
    const float4* self = hb + (size_t)n * (DP / 4);
    float4 a0 = self[lane];
    float4 a1 = self[lane + 32];
    float4 a2 = (lane < DP / 4 - 64) ? self[lane + 64] : make_float4(0.f, 0.f, 0.f, 0.f);
    for (int e = beg; e < end; e++) {
        int s = g_csrc[e];
        const float4* sr = hb + (size_t)s * (DP / 4);
        float4 v0 = sr[lane];
        float4 v1 = sr[lane + 32];
        a0.x += v0.x; a0.y += v0.y; a0.z += v0.z; a0.w += v0.w;
        a1.x += v1.x; a1.y += v1.y; a1.z += v1.z; a1.w += v1.w;
        if (lane < DP / 4 - 64) {
            float4 v2 = sr[lane + 64];
            a2.x += v2.x; a2.y += v2.y; a2.z += v2.z; a2.w += v2.w;
        }
    }
    float4* d = (float4*)(g_agg + (size_t)n * DP);
    d[lane] = a0;
    d[lane + 32] = a1;
    if (lane < DP / 4 - 64) d[lane + 64] = a2;
}

// ---------------- fused init: x -> h (padded), pool depth0 + counts ----------------
// 320 threads/block, PR rows per block; batch is sorted -> segment-reduce pooling.
__global__ void k_initfuse(const float* __restrict__ x) {
    int c = threadIdx.x;  // 0..319
    int r0 = blockIdx.x * PR;
    int rend = min(r0 + PR, NN);
    if (r0 >= NN) return;
    int curg = g_batch[r0];
    float acc = 0.f;
    int cnt = 0;
    for (int r = r0; r < rend; r++) {
        int gg = g_batch[r];
        if (gg != curg) {
            atomicAdd(&g_pooled[(size_t)curg * DP + c], acc);
            if (c == 0) atomicAdd(&g_cnt[curg], (float)cnt);
            curg = gg; acc = 0.f; cnt = 0;
        }
        float v = (c < DD) ? x[(size_t)r * DD + c] : 0.f;
        g_h[(size_t)r * DP + c] = v;
        acc += v;
        cnt++;
    }
    atomicAdd(&g_pooled[(size_t)curg * DP + c], acc);
    if (c == 0) atomicAdd(&g_cnt[curg], (float)cnt);
}

// stats -> per-column scale/shift (one block of DP threads)
__global__ void k_bnprep(int slot, const float* __restrict__ gamma,
                         const float* __restrict__ beta) {
    int c = threadIdx.x;
    if (c >= DP) return;
    float sc = 0.f, sh = 0.f;
    if (c < DD) {
        const float invn = 1.0f / (float)NN;
        float mean = g_sum[slot * DP + c] * invn;
        float var = g_sq[slot * DP + c] * invn - mean * mean;
        float istd = rsqrtf(var + BN_EPS);
        sc = istd * gamma[c];
        sh = beta[c] - mean * sc;
    }
    g_scale[slot * DP + c] = sc;
    g_shift[slot * DP + c] = sh;
}

// ---------------- fused BN2: h = relu(bn(zb)); pool into depth ----------------
// 320 threads/block, PR rows; segment-reduce pooling (batch sorted).
__global__ void k_bnfuse(int slot, int depth) {
    int c = threadIdx.x;  // 0..319
    int r0 = blockIdx.x * PR;
    int rend = min(r0 + PR, NN);
    if (r0 >= NN) return;
    float scl = g_scale[slot * DP + c];
    float shf = g_shift[slot * DP + c];
    float* pbase = g_pooled + (size_t)depth * NGG * DP;
    int curg = g_batch[r0];
    float acc = 0.f;
    for (int r = r0; r < rend; r++) {
        int gg = g_batch[r];
        if (gg != curg) {
            atomicAdd(&pbase[(size_t)curg * DP + c], acc);
            curg = gg; acc = 0.f;
        }
        float v = g_zb[(size_t)r * DP + c];
        v = fmaxf(fmaf(v, scl, shf), 0.f);
        g_h[(size_t)r * DP + c] = v;
        acc += v;
    }
    atomicAdd(&pbase[(size_t)curg * DP + c], acc);
}

// ---------------- TF32 tensor-core GEMM, stats fused in epilogue ----------------
// asel: 0 -> A = g_agg, 1 -> A = g_z.  osel: 0 -> Out = g_z, 1 -> Out = g_zb.
// FUSE=1: A transformed v = relu(v*scale+shift) on load (BN applied on the fly).
#define BKC 32
#define ASTRIDE 36
#define BSTRIDE 136
#define ATILE (128 * ASTRIDE)
#define BTILE (BKC * BSTRIDE)
#define BUFSZ (ATILE + BTILE)
#define GEMM_SMEM (2 * BUFSZ * 4)  // 71680 bytes

__device__ __forceinline__ void cpa16(uint32_t dst, const void* src, bool pred) {
    int sz = pred ? 16 : 0;
    asm volatile("cp.async.cg.shared.global [%0], [%1], 16, %2;\n"
                 :: "r"(dst), "l"(src), "r"(sz));
}

template <int FUSE>
__global__ void __launch_bounds__(256) k_gemm(int asel, int osel,
                                              int which, int layer,
                                              int slot_in, int slot_out) {
    extern __shared__ float sm[];
    const float* __restrict__ Asrc = asel ? g_z : g_agg;   // device-side symbol resolve
    float* __restrict__ Out = osel ? g_zb : g_z;
    const float* __restrict__ Bw = g_W + ((size_t)which * LL + layer) * DP * DP;
    const float* __restrict__ bias = g_bias + ((size_t)which * LL + layer) * DP;
    const float* __restrict__ scl = g_scale + (size_t)slot_in * DP;
    const float* __restrict__ shf = g_shift + (size_t)slot_in * DP;
    const int bm = blockIdx.y * 128;
    const int bn = blockIdx.x * 128;
    const int tid = threadIdx.x;
    const int lane = tid & 31, wid = tid >> 5;
    const int wm = (wid & 1) << 6;
    const int wn = (wid >> 1) << 5;
    const int gid = lane >> 2, tk = lane & 3;

    float c[4][4][4];
#pragma unroll
    for (int i = 0; i < 4; i++)
#pragma unroll
        for (int j = 0; j < 4; j++)
#pragma unroll
            for (int f = 0; f < 4; f++) c[i][j][f] = 0.f;

    const int ar = tid >> 3;         // 0..31
    const int av = (tid & 7) << 2;   // 0..28
    const int br = tid >> 5;         // 0..7
    const int bv = (tid & 31) << 2;  // 0..124
    const bool bvalid = (bn + bv) < DP;

    uint32_t smb = (uint32_t)__cvta_generic_to_shared(sm);

    // ---------- prologue ----------
    if (FUSE) {
        float4 areg[4];
#pragma unroll
        for (int p = 0; p < 4; p++) {
            int gr = bm + ar + p * 32;
            areg[p] = (gr < NN) ? *(const float4*)(Asrc + (size_t)gr * DP + av)
                                : make_float4(0.f, 0.f, 0.f, 0.f);
        }
#pragma unroll
        for (int p = 0; p < 4; p++) {
            int kr = br + p * 8;
            const float* bsrc = Bw + (size_t)kr * DP + (bvalid ? bn + bv : 0);
            cpa16(smb + (uint32_t)((ATILE + kr * BSTRIDE + bv) * 4), bsrc, bvalid);
        }
        asm volatile("cp.async.commit_group;\n");
        float sc0 = scl[av], sc1 = scl[av + 1], sc2 = scl[av + 2], sc3 = scl[av + 3];
        float sh0 = shf[av], sh1 = shf[av + 1], sh2 = shf[av + 2], sh3 = shf[av + 3];
#pragma unroll
        for (int p = 0; p < 4; p++) {
            float4 v = areg[p];
            v.x = fmaxf(fmaf(v.x, sc0, sh0), 0.f);
            v.y = fmaxf(fmaf(v.y, sc1, sh1), 0.f);
            v.z = fmaxf(fmaf(v.z, sc2, sh2), 0.f);
            v.w = fmaxf(fmaf(v.w, sc3, sh3), 0.f);
            float* d = sm + (ar + p * 32) * ASTRIDE + av;
            d[0] = v.x; d[1] = v.y; d[2] = v.z; d[3] = v.w;
        }
    } else {
#pragma unroll
        for (int p = 0; p < 4; p++) {
            int gr = bm + ar + p * 32;
            const float* asrc = Asrc + (size_t)(gr < NN ? gr : 0) * DP + av;
            cpa16(smb + (uint32_t)(((ar + p * 32) * ASTRIDE + av) * 4), asrc, gr < NN);
            int kr = br + p * 8;
            const float* bsrc = Bw + (size_t)kr * DP + (bvalid ? bn + bv : 0);
            cpa16(smb + (uint32_t)((ATILE + kr * BSTRIDE + bv) * 4), bsrc, bvalid);
        }
        asm volatile("cp.async.commit_group;\n");
    }

    int buf = 0;
#pragma unroll 1
    for (int k0 = 0; k0 < DP; k0 += BKC) {
        const bool has = (k0 + BKC < DP);
        float4 areg[4];
        float sc0, sc1, sc2, sc3, sh0, sh1, sh2, sh3;
        if (has) {
            int nb = buf ^ 1;
            int k1 = k0 + BKC;
            if (FUSE) {
#pragma unroll
                for (int p = 0; p < 4; p++) {
                    int gr = bm + ar + p * 32;
                    areg[p] = (gr < NN)
                        ? *(const float4*)(Asrc + (size_t)gr * DP + k1 + av)
                        : make_float4(0.f, 0.f, 0.f, 0.f);
                }
                sc0 = scl[k1 + av]; sc1 = scl[k1 + av + 1];
                sc2 = scl[k1 + av + 2]; sc3 = scl[k1 + av + 3];
                sh0 = shf[k1 + av]; sh1 = shf[k1 + av + 1];
                sh2 = shf[k1 + av + 2]; sh3 = shf[k1 + av + 3];
#pragma unroll
                for (int p = 0; p < 4; p++) {
                    int kr = k1 + br + p * 8;
                    const float* bsrc = Bw + (size_t)kr * DP + (bvalid ? bn + bv : 0);
                    cpa16(smb + (uint32_t)((nb * BUFSZ + ATILE + (br + p * 8) * BSTRIDE + bv) * 4),
                          bsrc, bvalid);
                }
            } else {
#pragma unroll
                for (int p = 0; p < 4; p++) {
                    int gr = bm + ar + p * 32;
                    const float* asrc = Asrc + (size_t)(gr < NN ? gr : 0) * DP + k1 + av;
                    cpa16(smb + (uint32_t)((nb * BUFSZ + (ar + p * 32) * ASTRIDE + av) * 4),
                          asrc, gr < NN);
                    int kr = k1 + br + p * 8;
                    const float* bsrc = Bw + (size_t)kr * DP + (bvalid ? bn + bv : 0);
                    cpa16(smb + (uint32_t)((nb * BUFSZ + ATILE + (br + p * 8) * BSTRIDE + bv) * 4),
                          bsrc, bvalid);
                }
            }
            asm volatile("cp.async.commit_group;\n");
            asm volatile("cp.async.wait_group 1;\n");
        } else {
            asm volatile("cp.async.wait_group 0;\n");
        }
        __syncthreads();
        const float* As = sm + buf * BUFSZ;
        const float* Bs = As + ATILE;
#pragma unroll
        for (int ks = 0; ks < BKC; ks += 8) {
            uint32_t a[4][4], b[4][2];
#pragma unroll
            for (int mt = 0; mt < 4; mt++) {
                const float* ap = As + (wm + mt * 16 + gid) * ASTRIDE + ks + tk;
                a[mt][0] = __float_as_uint(ap[0]);
                a[mt][1] = __float_as_uint(ap[8 * ASTRIDE]);
                a[mt][2] = __float_as_uint(ap[4]);
                a[mt][3] = __float_as_uint(ap[8 * ASTRIDE + 4]);
            }
#pragma unroll
            for (int nt = 0; nt < 4; nt++) {
                const float* bp = Bs + (ks + tk) * BSTRIDE + wn + nt * 8 + gid;
                b[nt][0] = __float_as_uint(bp[0]);
                b[nt][1] = __float_as_uint(bp[4 * BSTRIDE]);
            }
#pragma unroll
            for (int mt = 0; mt < 4; mt++)
#pragma unroll
                for (int nt = 0; nt < 4; nt++)
                    asm volatile(
                        "mma.sync.aligned.m16n8k8.row.col.f32.tf32.tf32.f32 "
                        "{%0,%1,%2,%3}, {%4,%5,%6,%7}, {%8,%9}, {%0,%1,%2,%3};\n"
                        : "+f"(c[mt][nt][0]), "+f"(c[mt][nt][1]),
                          "+f"(c[mt][nt][2]), "+f"(c[mt][nt][3])
                        : "r"(a[mt][0]), "r"(a[mt][1]), "r"(a[mt][2]), "r"(a[mt][3]),
                          "r"(b[nt][0]), "r"(b[nt][1]));
        }
        __syncthreads();
        if (FUSE && has) {
            int nb = buf ^ 1;
#pragma unroll
            for (int p = 0; p < 4; p++) {
                float4 v = areg[p];
                v.x = fmaxf(fmaf(v.x, sc0, sh0), 0.f);
                v.y = fmaxf(fmaf(v.y, sc1, sh1), 0.f);
                v.z = fmaxf(fmaf(v.z, sc2, sh2), 0.f);
                v.w = fmaxf(fmaf(v.w, sc3, sh3), 0.f);
                float* d = sm + nb * BUFSZ + (ar + p * 32) * ASTRIDE + av;
                d[0] = v.x; d[1] = v.y; d[2] = v.z; d[3] = v.w;
            }
        }
        buf ^= 1;
    }

    // ---------- epilogue: store + bias, fused column stats ----------
    float* Sg = g_sum + (size_t)slot_out * DP;
    float* Qg = g_sq + (size_t)slot_out * DP;
#pragma unroll
    for (int nt = 0; nt < 4; nt++) {
        int c0 = bn + wn + nt * 8 + 2 * tk;
        if (c0 >= DP) continue;
        float b0 = bias[c0], b1 = bias[c0 + 1];
        float s0 = 0.f, q0 = 0.f, s1 = 0.f, q1 = 0.f;
#pragma unroll
        for (int mt = 0; mt < 4; mt++) {
            int r0 = bm + wm + mt * 16 + gid;
            float v00 = c[mt][nt][0] + b0, v01 = c[mt][nt][1] + b1;
            float v10 = c[mt][nt][2] + b0, v11 = c[mt][nt][3] + b1;
            if (r0 < NN) {
                *(float2*)(Out + (size_t)r0 * DP + c0) = make_float2(v00, v01);
                s0 += v00; q0 += v00 * v00;
                s1 += v01; q1 += v01 * v01;
            }
            if (r0 + 8 < NN) {
                *(float2*)(Out + (size_t)(r0 + 8) * DP + c0) = make_float2(v10, v11);
                s0 += v10; q0 += v10 * v10;
                s1 += v11; q1 += v11 * v11;
            }
        }
#pragma unroll
        for (int off = 16; off >= 4; off >>= 1) {
            s0 += __shfl_xor_sync(0xffffffffu, s0, off);
            q0 += __shfl_xor_sync(0xffffffffu, q0, off);
            s1 += __shfl_xor_sync(0xffffffffu, s1, off);
            q1 += __shfl_xor_sync(0xffffffffu, q1, off);
        }
        if (gid == 0) {
            atomicAdd(&Sg[c0], s0);
            atomicAdd(&Qg[c0], q0);
            atomicAdd(&Sg[c0 + 1], s1);
            atomicAdd(&Qg[c0 + 1], q1);
        }
    }
}

// ---------------- readout ----------------
__global__ void k_readout(const float* __restrict__ fcW, const float* __restrict__ fcb,
                          float* __restrict__ out) {
    int g = blockIdx.x;
    int c = threadIdx.x;  // 128
    float inv = 1.0f / fmaxf(g_cnt[g], 1.0f);
    float acc = 0.f;
#pragma unroll
    for (int i = 0; i <= LL; ++i) {
        const float* p = g_pooled + ((size_t)i * NGG + g) * DP;
        const float* W = fcW + (size_t)i * DD * CC;
        float a = 0.f;
        for (int k = 0; k < DD; ++k)
            a += p[k] * W[k * CC + c];
        acc += inv * a + fcb[i * CC + c];
    }
    out[g * CC + c] = acc;
}

// ---------------- launch ----------------
extern "C" void kernel_launch(void* const* d_in, const int* in_sizes, int n_in,
                              void* d_out, int out_size) {
    const float* x       = (const float*)d_in[0];
    const void*  edg_raw = d_in[1];
    const void*  bat_raw = d_in[2];
    const float* mlp_W1  = (const float*)d_in[3];
    const float* mlp_b1  = (const float*)d_in[4];
    const float* mlp_g1  = (const float*)d_in[5];
    const float* mlp_be1 = (const float*)d_in[6];
    const float* mlp_W2  = (const float*)d_in[7];
    const float* mlp_b2  = (const float*)d_in[8];
    const float* bn_g    = (const float*)d_in[9];
    const float* bn_b    = (const float*)d_in[10];
    const float* fc_W    = (const float*)d_in[11];
    const float* fc_b    = (const float*)d_in[12];
    float* out = (float*)d_out;

    static bool done = false;
    if (!done) {
        cudaFuncSetAttribute(k_gemm<0>, cudaFuncAttributeMaxDynamicSharedMemorySize, GEMM_SMEM);
        cudaFuncSetAttribute(k_gemm<1>, cudaFuncAttributeMaxDynamicSharedMemorySize, GEMM_SMEM);
        done = true;
    }

    // dtype normalization (int64 vs int32)
    k_zero_flags<<<1, 32>>>();
    k_detect<<<256, 256>>>((const int*)edg_raw, 2 * EE, 0);
    k_detect<<<64, 256>>>((const int*)bat_raw, NN, 1);
    k_convert_edge<<<(2 * EE + 255) / 256, 256>>>(edg_raw);
    k_convert_batch<<<(NN + 255) / 256, 256>>>(bat_raw);

    // CSR build (once)
    k_zero_deg<<<(NN + 256) / 256, 256>>>();
    k_hist<<<(EE + 255) / 256, 256>>>();
    k_scan<<<1, 1024>>>();
    k_copycur<<<(NN + 255) / 256, 256>>>();
    k_place<<<(EE + 255) / 256, 256>>>();

    // param staging + init
    k_padW<<<1024, 256>>>(mlp_W1, mlp_W2);
    k_padB<<<(2 * LL * DP + 255) / 256, 256>>>(mlp_b1, mlp_b2);
    k_zero_pool<<<1024, 256>>>();
    k_zero_stats<<<(NSLOT * DP + 255) / 256, 256>>>();
    k_initfuse<<<(NN + PR - 1) / PR, DP>>>(x);

    dim3 ggrid((DP + 127) / 128, (NN + 127) / 128);
    for (int i = 0; i < LL; ++i) {
        k_aggregate<<<(NN * 32 + 255) / 256, 256>>>();
        // GEMM1: z = agg @ W1 + b1, stats slot 2i
        k_gemm<0><<<ggrid, 256, GEMM_SMEM>>>(0, 0, 0, i, 0, 2 * i);
        k_bnprep<<<1, DP>>>(2 * i, mlp_g1 + i * DD, mlp_be1 + i * DD);
        // GEMM2: zb = relu(bn1(z)) @ W2 + b2, BN fused on A-load, stats slot 2i+1
        k_gemm<1><<<ggrid, 256, GEMM_SMEM>>>(1, 1, 1, i, 2 * i, 2 * i + 1);
        k_bnprep<<<1, DP>>>(2 * i + 1, bn_g + i * DD, bn_b + i * DD);
        // h = relu(bn2(zb)); pool depth i+1
        k_bnfuse<<<(NN + PR - 1) / PR, DP>>>(2 * i + 1, i + 1);
    }
    k_readout<<<NGG, CC>>>(fc_W, fc_b, out);
}